// round 14
// baseline (speedup 1.0000x reference)
#include <cuda_runtime.h>
#include <cuda_bf16.h>
#include <math.h>
#include <stdint.h>

// ---------------- problem constants ----------------
#define B_    8
#define SEQ   1024
#define CDIM  768
#define NH    12
#define HD    64
#define QKVC  (3 * CDIM)      // 2304
#define MROWS (B_ * SEQ)      // 8192

// ---------------- scratch (allocation-free rule: device globals) ----------
__device__ float g_qkv[(size_t)MROWS * QKVC];  // 75.5 MB
__device__ float g_o  [(size_t)MROWS * CDIM];  // 25 MB

// ---------------- tf32 mma helpers ----------------
__device__ __forceinline__ uint32_t f2tf(float x) {
    uint32_t u;
    asm("cvt.rna.tf32.f32 %0, %1;" : "=r"(u) : "f"(x));
    return u;
}

__device__ __forceinline__ void mma8(float* c, const uint32_t* a, const uint32_t* b) {
    asm volatile(
        "mma.sync.aligned.m16n8k8.row.col.f32.tf32.tf32.f32 "
        "{%0,%1,%2,%3}, {%4,%5,%6,%7}, {%8,%9}, {%0,%1,%2,%3};"
        : "+f"(c[0]), "+f"(c[1]), "+f"(c[2]), "+f"(c[3])
        : "r"(a[0]), "r"(a[1]), "r"(a[2]), "r"(a[3]), "r"(b[0]), "r"(b[1]));
}

#define CP_ASYNC16(dst_u32, src) \
    asm volatile("cp.async.cg.shared.global [%0], [%1], 16;" :: "r"(dst_u32), "l"(src))
#define CP_COMMIT() asm volatile("cp.async.commit_group;")
#define CP_WAIT1()  asm volatile("cp.async.wait_group 1;")
#define CP_WAIT0()  asm volatile("cp.async.wait_group 0;")

// =========================================================================
// TF32 GEMM: C[M,N] = A[M,K] @ B[K,N] (+bias). 128x128x32 tile, 256 threads,
// 8 warps each 64x32, cp.async double-buffered. M%128==0,N%128==0,K%32==0.
// smem strides padded to ≡8 (mod 32) words -> conflict-free frag loads.
// =========================================================================
#define BM 128
#define BN 128
#define BK 32
#define AST_G 40    // A row stride (BK + 8)
#define BST_G 136   // B row stride (BN + 8)
#define GEMM_SMEM ((2 * BM * AST_G + 2 * BK * BST_G) * (int)sizeof(float))  // 75776

__global__ __launch_bounds__(256, 2)
void gemm_tf32(const float* __restrict__ A, const float* __restrict__ Bm,
               float* __restrict__ C, int M, int N, int K,
               const float* __restrict__ bias) {
    extern __shared__ float sm[];
    float* As = sm;                       // [2][BM][AST_G]
    float* Bs = sm + 2 * BM * AST_G;      // [2][BK][BST_G]

    const int tid  = threadIdx.x;
    const int bm   = blockIdx.y * BM;
    const int bn   = blockIdx.x * BN;
    const int warp = tid >> 5, lane = tid & 31;
    const int g = lane >> 2, t = lane & 3;
    const int mbase = (warp >> 2) * 64;
    const int nbase = (warp & 3) * 32;

    float acc[4][4][4];
    #pragma unroll
    for (int i = 0; i < 4; i++)
        #pragma unroll
        for (int j = 0; j < 4; j++)
            #pragma unroll
            for (int r = 0; r < 4; r++) acc[i][j][r] = 0.f;

    // ---- tile loaders (1024 float4 each for A and B) ----
    #define LOAD_TILES(stage, k0)                                              \
    do {                                                                       \
        float* as = As + (stage) * BM * AST_G;                                 \
        float* bs = Bs + (stage) * BK * BST_G;                                 \
        _Pragma("unroll")                                                      \
        for (int i = 0; i < 4; i++) {                                          \
            int idx = tid + i * 256;                                           \
            int r = idx >> 3, c = (idx & 7) * 4;                               \
            uint32_t d = (uint32_t)__cvta_generic_to_shared(as + r * AST_G + c); \
            CP_ASYNC16(d, A + (size_t)(bm + r) * K + (k0) + c);                \
        }                                                                      \
        _Pragma("unroll")                                                      \
        for (int i = 0; i < 4; i++) {                                          \
            int idx = tid + i * 256;                                           \
            int r = idx >> 5, c = (idx & 31) * 4;                              \
            uint32_t d = (uint32_t)__cvta_generic_to_shared(bs + r * BST_G + c); \
            CP_ASYNC16(d, Bm + (size_t)((k0) + r) * N + bn + c);               \
        }                                                                      \
    } while (0)

    const int nk = K / BK;
    LOAD_TILES(0, 0);
    CP_COMMIT();

    for (int kt = 0; kt < nk; kt++) {
        const int s = kt & 1;
        if (kt + 1 < nk) {
            LOAD_TILES(s ^ 1, (kt + 1) * BK);
            CP_COMMIT();
            CP_WAIT1();
        } else {
            CP_WAIT0();
        }
        __syncthreads();

        const float* as = As + s * BM * AST_G;
        const float* bs = Bs + s * BK * BST_G;
        #pragma unroll
        for (int kc = 0; kc < 4; kc++) {
            const int k0 = kc * 8;
            uint32_t af[4][4], bf[4][2];
            #pragma unroll
            for (int mi = 0; mi < 4; mi++) {
                const float* p = as + (mbase + mi * 16 + g) * AST_G + k0 + t;
                af[mi][0] = f2tf(p[0]);
                af[mi][2] = f2tf(p[4]);
                af[mi][1] = f2tf(p[8 * AST_G]);
                af[mi][3] = f2tf(p[8 * AST_G + 4]);
            }
            #pragma unroll
            for (int ni = 0; ni < 4; ni++) {
                const float* p = bs + (k0 + t) * BST_G + nbase + ni * 8 + g;
                bf[ni][0] = f2tf(p[0]);
                bf[ni][1] = f2tf(p[4 * BST_G]);
            }
            #pragma unroll
            for (int mi = 0; mi < 4; mi++)
                #pragma unroll
                for (int ni = 0; ni < 4; ni++)
                    mma8(acc[mi][ni], af[mi], bf[ni]);
        }
        __syncthreads();
    }

    // epilogue
    #pragma unroll
    for (int mi = 0; mi < 4; mi++) {
        const int row0 = bm + mbase + mi * 16 + g;
        #pragma unroll
        for (int ni = 0; ni < 4; ni++) {
            const int col = bn + nbase + ni * 8 + 2 * t;
            float2 v0 = make_float2(acc[mi][ni][0], acc[mi][ni][1]);
            float2 v1 = make_float2(acc[mi][ni][2], acc[mi][ni][3]);
            if (bias) {
                const float bx = bias[col], by = bias[col + 1];
                v0.x += bx; v0.y += by; v1.x += bx; v1.y += by;
            }
            *(float2*)(C + (size_t)row0 * N + col)       = v0;
            *(float2*)(C + (size_t)(row0 + 8) * N + col) = v1;
        }
    }
    #undef LOAD_TILES
}

// =========================================================================
// TF32 flash attention. CTA = (b, h, 128-row Q tile), 256 threads = 8 warps.
// Warp w owns S/O rows [16w, 16w+16) x all 64 cols -> softmax reduce is a
// 4-thread shfl; P rows are warp-private (syncwarp only before PV).
// =========================================================================
#define BQ  128
#define BKV 64
#define AST 72   // padded row stride (64 + 8): banks = 8g+t, conflict-free
#define FA_SMEM ((2 * BQ * AST + 2 * BKV * AST) * (int)sizeof(float))  // 110592

__global__ __launch_bounds__(256)
void attn_tf32(const float* __restrict__ qkv, float* __restrict__ O) {
    extern __shared__ float sm[];
    float* Qs = sm;                 // [128][72]
    float* Ks = Qs + BQ * AST;      // [64][72]
    float* Vs = Ks + BKV * AST;     // [64][72]
    float* Ps = Vs + BKV * AST;     // [128][72]

    const int tid  = threadIdx.x;
    const int warp = tid >> 5, lane = tid & 31;
    const int g = lane >> 2, t = lane & 3;
    const int q0 = blockIdx.x * BQ;
    const int h  = blockIdx.y;
    const int b  = blockIdx.z;
    const int mrow = warp * 16;

    const float* base = qkv + (size_t)b * SEQ * QKVC + h * HD;

    // load Q tile, scale folded (1/sqrt(64) = 0.125)
    #pragma unroll
    for (int i = 0; i < 8; i++) {
        const int idx = tid + i * 256;
        const int r = idx >> 4, c = (idx & 15) * 4;
        float4 v = *(const float4*)(base + (size_t)(q0 + r) * QKVC + c);
        float* dst = Qs + r * AST + c;
        dst[0] = v.x * 0.125f; dst[1] = v.y * 0.125f;
        dst[2] = v.z * 0.125f; dst[3] = v.w * 0.125f;
    }

    float oacc[8][4];
    #pragma unroll
    for (int ni = 0; ni < 8; ni++)
        #pragma unroll
        for (int r = 0; r < 4; r++) oacc[ni][r] = 0.f;
    float m0 = -INFINITY, m1 = -INFINITY, l0 = 0.f, l1 = 0.f;

    for (int kt = 0; kt < SEQ / BKV; kt++) {
        __syncthreads();   // prior-iteration Ks/Vs/Ps readers done
        #pragma unroll
        for (int i = 0; i < 4; i++) {
            const int idx = tid + i * 256;
            const int r = idx >> 4, c = (idx & 15) * 4;
            const float* rp = base + (size_t)(kt * BKV + r) * QKVC + c;
            *(float4*)(Ks + r * AST + c) = *(const float4*)(rp + CDIM);
            *(float4*)(Vs + r * AST + c) = *(const float4*)(rp + 2 * CDIM);
        }
        __syncthreads();

        // ---- S = Q K^T (warp: 16 rows x 64 cols = 1x8 mma tiles, 8 kchunks)
        float sacc[8][4];
        #pragma unroll
        for (int ni = 0; ni < 8; ni++)
            #pragma unroll
            for (int r = 0; r < 4; r++) sacc[ni][r] = 0.f;

        #pragma unroll
        for (int kc = 0; kc < 8; kc++) {
            const int k0 = kc * 8;
            uint32_t af[4];
            const float* qp = Qs + (mrow + g) * AST + k0 + t;
            af[0] = f2tf(qp[0]);
            af[2] = f2tf(qp[4]);
            af[1] = f2tf(qp[8 * AST]);
            af[3] = f2tf(qp[8 * AST + 4]);
            #pragma unroll
            for (int ni = 0; ni < 8; ni++) {
                uint32_t bf[2];
                const float* kp = Ks + (ni * 8 + g) * AST + k0 + t;
                bf[0] = f2tf(kp[0]);
                bf[1] = f2tf(kp[4]);
                mma8(sacc[ni], af, bf);
            }
        }

        // ---- online softmax (rows g and g+8 of this warp tile)
        float mx0 = -INFINITY, mx1 = -INFINITY;
        #pragma unroll
        for (int ni = 0; ni < 8; ni++) {
            mx0 = fmaxf(mx0, fmaxf(sacc[ni][0], sacc[ni][1]));
            mx1 = fmaxf(mx1, fmaxf(sacc[ni][2], sacc[ni][3]));
        }
        mx0 = fmaxf(mx0, __shfl_xor_sync(0xffffffffu, mx0, 1));
        mx0 = fmaxf(mx0, __shfl_xor_sync(0xffffffffu, mx0, 2));
        mx1 = fmaxf(mx1, __shfl_xor_sync(0xffffffffu, mx1, 1));
        mx1 = fmaxf(mx1, __shfl_xor_sync(0xffffffffu, mx1, 2));

        const float mn0 = fmaxf(m0, mx0), mn1 = fmaxf(m1, mx1);
        const float a0 = __expf(m0 - mn0), a1 = __expf(m1 - mn1);
        float rs0 = 0.f, rs1 = 0.f;
        #pragma unroll
        for (int ni = 0; ni < 8; ni++) {
            sacc[ni][0] = __expf(sacc[ni][0] - mn0);
            sacc[ni][1] = __expf(sacc[ni][1] - mn0);
            sacc[ni][2] = __expf(sacc[ni][2] - mn1);
            sacc[ni][3] = __expf(sacc[ni][3] - mn1);
            rs0 += sacc[ni][0] + sacc[ni][1];
            rs1 += sacc[ni][2] + sacc[ni][3];
        }
        rs0 += __shfl_xor_sync(0xffffffffu, rs0, 1);
        rs0 += __shfl_xor_sync(0xffffffffu, rs0, 2);
        rs1 += __shfl_xor_sync(0xffffffffu, rs1, 1);
        rs1 += __shfl_xor_sync(0xffffffffu, rs1, 2);
        l0 = l0 * a0 + rs0;  l1 = l1 * a1 + rs1;
        m0 = mn0;            m1 = mn1;
        #pragma unroll
        for (int ni = 0; ni < 8; ni++) {
            oacc[ni][0] *= a0; oacc[ni][1] *= a0;
            oacc[ni][2] *= a1; oacc[ni][3] *= a1;
        }

        // ---- stage P in smem (warp-private rows) ----
        #pragma unroll
        for (int ni = 0; ni < 8; ni++) {
            *(float2*)(Ps + (mrow + g) * AST + ni * 8 + 2 * t) =
                make_float2(sacc[ni][0], sacc[ni][1]);
            *(float2*)(Ps + (mrow + 8 + g) * AST + ni * 8 + 2 * t) =
                make_float2(sacc[ni][2], sacc[ni][3]);
        }
        __syncwarp();

        // ---- O += P @ V ----
        #pragma unroll
        for (int kc = 0; kc < 8; kc++) {
            const int k0 = kc * 8;
            uint32_t af[4];
            const float* pp = Ps + (mrow + g) * AST + k0 + t;
            af[0] = f2tf(pp[0]);
            af[2] = f2tf(pp[4]);
            af[1] = f2tf(pp[8 * AST]);
            af[3] = f2tf(pp[8 * AST + 4]);
            #pragma unroll
            for (int ni = 0; ni < 8; ni++) {
                uint32_t bf[2];
                bf[0] = f2tf(Vs[(k0 + t) * AST + ni * 8 + g]);
                bf[1] = f2tf(Vs[(k0 + t + 4) * AST + ni * 8 + g]);
                mma8(oacc[ni], af, bf);
            }
        }
    }

    // ---- epilogue ----
    const float il0 = 1.0f / l0, il1 = 1.0f / l1;
    const size_t row0 = (size_t)(b * SEQ + q0 + mrow + g);
    #pragma unroll
    for (int ni = 0; ni < 8; ni++) {
        const int col = h * HD + ni * 8 + 2 * t;
        *(float2*)(O + row0 * CDIM + col) =
            make_float2(oacc[ni][0] * il0, oacc[ni][1] * il0);
        *(float2*)(O + (row0 + 8) * CDIM + col) =
            make_float2(oacc[ni][2] * il1, oacc[ni][3] * il1);
    }
}

// =========================================================================
// launch
// =========================================================================
extern "C" void kernel_launch(void* const* d_in, const int* in_sizes, int n_in,
                              void* d_out, int out_size) {
    const float* x      = (const float*)d_in[0];
    const float* w_qkv  = (const float*)d_in[1];
    const float* w_proj = (const float*)d_in[2];
    const float* b_proj = (const float*)d_in[3];
    float* out = (float*)d_out;

    float *qkv_ptr, *o_ptr;
    cudaGetSymbolAddress((void**)&qkv_ptr, g_qkv);
    cudaGetSymbolAddress((void**)&o_ptr,   g_o);

    cudaFuncSetAttribute(gemm_tf32,
                         cudaFuncAttributeMaxDynamicSharedMemorySize, GEMM_SMEM);
    cudaFuncSetAttribute(attn_tf32,
                         cudaFuncAttributeMaxDynamicSharedMemorySize, FA_SMEM);

    // 1) QKV projection: [8192,768] @ [768,2304]
    {
        dim3 grid(QKVC / BN, MROWS / BM);
        gemm_tf32<<<grid, 256, GEMM_SMEM>>>(x, w_qkv, qkv_ptr,
                                            MROWS, QKVC, CDIM, nullptr);
    }
    // 2) flash attention
    {
        dim3 grid(SEQ / BQ, NH, B_);
        attn_tf32<<<grid, 256, FA_SMEM>>>(qkv_ptr, o_ptr);
    }
    // 3) output projection + bias: [8192,768] @ [768,768]
    {
        dim3 grid(CDIM / BN, MROWS / BM);
        gemm_tf32<<<grid, 256, GEMM_SMEM>>>(o_ptr, w_proj, out,
                                            MROWS, CDIM, CDIM, b_proj);
    }
}

// round 15
// speedup vs baseline: 1.0028x; 1.0028x over previous
#include <cuda_runtime.h>
#include <cuda_bf16.h>
#include <math.h>
#include <stdint.h>

// ---------------- problem constants ----------------
#define B_    8
#define SEQ   1024
#define CDIM  768
#define NH    12
#define HD    64
#define QKVC  (3 * CDIM)      // 2304
#define MROWS (B_ * SEQ)      // 8192

// ---------------- scratch (allocation-free rule: device globals) ----------
__device__ float g_qkv[(size_t)MROWS * QKVC];  // 75.5 MB
__device__ float g_o  [(size_t)MROWS * CDIM];  // 25 MB

// ---------------- tf32 mma helpers ----------------
__device__ __forceinline__ uint32_t f2tf(float x) {
    uint32_t u;
    asm("cvt.rna.tf32.f32 %0, %1;" : "=r"(u) : "f"(x));
    return u;
}

__device__ __forceinline__ void mma8(float* c, const uint32_t* a, const uint32_t* b) {
    asm volatile(
        "mma.sync.aligned.m16n8k8.row.col.f32.tf32.tf32.f32 "
        "{%0,%1,%2,%3}, {%4,%5,%6,%7}, {%8,%9}, {%0,%1,%2,%3};"
        : "+f"(c[0]), "+f"(c[1]), "+f"(c[2]), "+f"(c[3])
        : "r"(a[0]), "r"(a[1]), "r"(a[2]), "r"(a[3]), "r"(b[0]), "r"(b[1]));
}

#define CP_ASYNC16(dst_u32, src) \
    asm volatile("cp.async.cg.shared.global [%0], [%1], 16;" :: "r"(dst_u32), "l"(src))
#define CP_COMMIT() asm volatile("cp.async.commit_group;")
#define CP_WAIT1()  asm volatile("cp.async.wait_group 1;")
#define CP_WAIT0()  asm volatile("cp.async.wait_group 0;")

// =========================================================================
// TF32 GEMM: C[M,N] = A[M,K] @ B[K,N] (+bias). 128x128x32 tile, 256 threads,
// 8 warps each 64x32, cp.async double-buffered. M%128==0,N%128==0,K%32==0.
// smem strides padded to ≡8 (mod 32) words -> conflict-free frag loads.
// =========================================================================
#define BM 128
#define BN 128
#define BK 32
#define AST_G 40    // A row stride (BK + 8)
#define BST_G 136   // B row stride (BN + 8)
#define GEMM_SMEM ((2 * BM * AST_G + 2 * BK * BST_G) * (int)sizeof(float))  // 75776

__global__ __launch_bounds__(256, 2)
void gemm_tf32(const float* __restrict__ A, const float* __restrict__ Bm,
               float* __restrict__ C, int M, int N, int K,
               const float* __restrict__ bias) {
    extern __shared__ float sm[];
    float* As = sm;                       // [2][BM][AST_G]
    float* Bs = sm + 2 * BM * AST_G;      // [2][BK][BST_G]

    const int tid  = threadIdx.x;
    const int bm   = blockIdx.y * BM;
    const int bn   = blockIdx.x * BN;
    const int warp = tid >> 5, lane = tid & 31;
    const int g = lane >> 2, t = lane & 3;
    const int mbase = (warp >> 2) * 64;
    const int nbase = (warp & 3) * 32;

    float acc[4][4][4];
    #pragma unroll
    for (int i = 0; i < 4; i++)
        #pragma unroll
        for (int j = 0; j < 4; j++)
            #pragma unroll
            for (int r = 0; r < 4; r++) acc[i][j][r] = 0.f;

    // ---- tile loaders (1024 float4 each for A and B) ----
    #define LOAD_TILES(stage, k0)                                              \
    do {                                                                       \
        float* as = As + (stage) * BM * AST_G;                                 \
        float* bs = Bs + (stage) * BK * BST_G;                                 \
        _Pragma("unroll")                                                      \
        for (int i = 0; i < 4; i++) {                                          \
            int idx = tid + i * 256;                                           \
            int r = idx >> 3, c = (idx & 7) * 4;                               \
            uint32_t d = (uint32_t)__cvta_generic_to_shared(as + r * AST_G + c); \
            CP_ASYNC16(d, A + (size_t)(bm + r) * K + (k0) + c);                \
        }                                                                      \
        _Pragma("unroll")                                                      \
        for (int i = 0; i < 4; i++) {                                          \
            int idx = tid + i * 256;                                           \
            int r = idx >> 5, c = (idx & 31) * 4;                              \
            uint32_t d = (uint32_t)__cvta_generic_to_shared(bs + r * BST_G + c); \
            CP_ASYNC16(d, Bm + (size_t)((k0) + r) * N + bn + c);               \
        }                                                                      \
    } while (0)

    const int nk = K / BK;
    LOAD_TILES(0, 0);
    CP_COMMIT();

    for (int kt = 0; kt < nk; kt++) {
        const int s = kt & 1;
        if (kt + 1 < nk) {
            LOAD_TILES(s ^ 1, (kt + 1) * BK);
            CP_COMMIT();
            CP_WAIT1();
        } else {
            CP_WAIT0();
        }
        __syncthreads();

        const float* as = As + s * BM * AST_G;
        const float* bs = Bs + s * BK * BST_G;
        #pragma unroll
        for (int kc = 0; kc < 4; kc++) {
            const int k0 = kc * 8;
            uint32_t af[4][4], bf[4][2];
            #pragma unroll
            for (int mi = 0; mi < 4; mi++) {
                const float* p = as + (mbase + mi * 16 + g) * AST_G + k0 + t;
                af[mi][0] = f2tf(p[0]);
                af[mi][2] = f2tf(p[4]);
                af[mi][1] = f2tf(p[8 * AST_G]);
                af[mi][3] = f2tf(p[8 * AST_G + 4]);
            }
            #pragma unroll
            for (int ni = 0; ni < 4; ni++) {
                const float* p = bs + (k0 + t) * BST_G + nbase + ni * 8 + g;
                bf[ni][0] = f2tf(p[0]);
                bf[ni][1] = f2tf(p[4 * BST_G]);
            }
            #pragma unroll
            for (int mi = 0; mi < 4; mi++)
                #pragma unroll
                for (int ni = 0; ni < 4; ni++)
                    mma8(acc[mi][ni], af[mi], bf[ni]);
        }
        __syncthreads();
    }

    // epilogue
    #pragma unroll
    for (int mi = 0; mi < 4; mi++) {
        const int row0 = bm + mbase + mi * 16 + g;
        #pragma unroll
        for (int ni = 0; ni < 4; ni++) {
            const int col = bn + nbase + ni * 8 + 2 * t;
            float2 v0 = make_float2(acc[mi][ni][0], acc[mi][ni][1]);
            float2 v1 = make_float2(acc[mi][ni][2], acc[mi][ni][3]);
            if (bias) {
                const float bx = bias[col], by = bias[col + 1];
                v0.x += bx; v0.y += by; v1.x += bx; v1.y += by;
            }
            *(float2*)(C + (size_t)row0 * N + col)       = v0;
            *(float2*)(C + (size_t)(row0 + 8) * N + col) = v1;
        }
    }
    #undef LOAD_TILES
}

// =========================================================================
// TF32 flash attention. CTA = (b, h, 128-row Q tile), 256 threads = 8 warps.
// Warp w owns S/O rows [16w, 16w+16) x all 64 cols -> softmax reduce is a
// 4-thread shfl; P rows are warp-private (syncwarp only before PV).
// =========================================================================
#define BQ  128
#define BKV 64
#define AST 72   // padded row stride (64 + 8): banks = 8g+t, conflict-free
#define FA_SMEM ((2 * BQ * AST + 2 * BKV * AST) * (int)sizeof(float))  // 110592

__global__ __launch_bounds__(256)
void attn_tf32(const float* __restrict__ qkv, float* __restrict__ O) {
    extern __shared__ float sm[];
    float* Qs = sm;                 // [128][72]
    float* Ks = Qs + BQ * AST;      // [64][72]
    float* Vs = Ks + BKV * AST;     // [64][72]
    float* Ps = Vs + BKV * AST;     // [128][72]

    const int tid  = threadIdx.x;
    const int warp = tid >> 5, lane = tid & 31;
    const int g = lane >> 2, t = lane & 3;
    const int q0 = blockIdx.x * BQ;
    const int h  = blockIdx.y;
    const int b  = blockIdx.z;
    const int mrow = warp * 16;

    const float* base = qkv + (size_t)b * SEQ * QKVC + h * HD;

    // load Q tile, scale folded (1/sqrt(64) = 0.125)
    #pragma unroll
    for (int i = 0; i < 8; i++) {
        const int idx = tid + i * 256;
        const int r = idx >> 4, c = (idx & 15) * 4;
        float4 v = *(const float4*)(base + (size_t)(q0 + r) * QKVC + c);
        float* dst = Qs + r * AST + c;
        dst[0] = v.x * 0.125f; dst[1] = v.y * 0.125f;
        dst[2] = v.z * 0.125f; dst[3] = v.w * 0.125f;
    }

    float oacc[8][4];
    #pragma unroll
    for (int ni = 0; ni < 8; ni++)
        #pragma unroll
        for (int r = 0; r < 4; r++) oacc[ni][r] = 0.f;
    float m0 = -INFINITY, m1 = -INFINITY, l0 = 0.f, l1 = 0.f;

    for (int kt = 0; kt < SEQ / BKV; kt++) {
        __syncthreads();   // prior-iteration Ks/Vs/Ps readers done
        #pragma unroll
        for (int i = 0; i < 4; i++) {
            const int idx = tid + i * 256;
            const int r = idx >> 4, c = (idx & 15) * 4;
            const float* rp = base + (size_t)(kt * BKV + r) * QKVC + c;
            *(float4*)(Ks + r * AST + c) = *(const float4*)(rp + CDIM);
            *(float4*)(Vs + r * AST + c) = *(const float4*)(rp + 2 * CDIM);
        }
        __syncthreads();

        // ---- S = Q K^T (warp: 16 rows x 64 cols = 1x8 mma tiles, 8 kchunks)
        float sacc[8][4];
        #pragma unroll
        for (int ni = 0; ni < 8; ni++)
            #pragma unroll
            for (int r = 0; r < 4; r++) sacc[ni][r] = 0.f;

        #pragma unroll
        for (int kc = 0; kc < 8; kc++) {
            const int k0 = kc * 8;
            uint32_t af[4];
            const float* qp = Qs + (mrow + g) * AST + k0 + t;
            af[0] = f2tf(qp[0]);
            af[2] = f2tf(qp[4]);
            af[1] = f2tf(qp[8 * AST]);
            af[3] = f2tf(qp[8 * AST + 4]);
            #pragma unroll
            for (int ni = 0; ni < 8; ni++) {
                uint32_t bf[2];
                const float* kp = Ks + (ni * 8 + g) * AST + k0 + t;
                bf[0] = f2tf(kp[0]);
                bf[1] = f2tf(kp[4]);
                mma8(sacc[ni], af, bf);
            }
        }

        // ---- online softmax (rows g and g+8 of this warp tile)
        float mx0 = -INFINITY, mx1 = -INFINITY;
        #pragma unroll
        for (int ni = 0; ni < 8; ni++) {
            mx0 = fmaxf(mx0, fmaxf(sacc[ni][0], sacc[ni][1]));
            mx1 = fmaxf(mx1, fmaxf(sacc[ni][2], sacc[ni][3]));
        }
        mx0 = fmaxf(mx0, __shfl_xor_sync(0xffffffffu, mx0, 1));
        mx0 = fmaxf(mx0, __shfl_xor_sync(0xffffffffu, mx0, 2));
        mx1 = fmaxf(mx1, __shfl_xor_sync(0xffffffffu, mx1, 1));
        mx1 = fmaxf(mx1, __shfl_xor_sync(0xffffffffu, mx1, 2));

        const float mn0 = fmaxf(m0, mx0), mn1 = fmaxf(m1, mx1);
        const float a0 = __expf(m0 - mn0), a1 = __expf(m1 - mn1);
        float rs0 = 0.f, rs1 = 0.f;
        #pragma unroll
        for (int ni = 0; ni < 8; ni++) {
            sacc[ni][0] = __expf(sacc[ni][0] - mn0);
            sacc[ni][1] = __expf(sacc[ni][1] - mn0);
            sacc[ni][2] = __expf(sacc[ni][2] - mn1);
            sacc[ni][3] = __expf(sacc[ni][3] - mn1);
            rs0 += sacc[ni][0] + sacc[ni][1];
            rs1 += sacc[ni][2] + sacc[ni][3];
        }
        rs0 += __shfl_xor_sync(0xffffffffu, rs0, 1);
        rs0 += __shfl_xor_sync(0xffffffffu, rs0, 2);
        rs1 += __shfl_xor_sync(0xffffffffu, rs1, 1);
        rs1 += __shfl_xor_sync(0xffffffffu, rs1, 2);
        l0 = l0 * a0 + rs0;  l1 = l1 * a1 + rs1;
        m0 = mn0;            m1 = mn1;
        #pragma unroll
        for (int ni = 0; ni < 8; ni++) {
            oacc[ni][0] *= a0; oacc[ni][1] *= a0;
            oacc[ni][2] *= a1; oacc[ni][3] *= a1;
        }

        // ---- stage P in smem (warp-private rows) ----
        #pragma unroll
        for (int ni = 0; ni < 8; ni++) {
            *(float2*)(Ps + (mrow + g) * AST + ni * 8 + 2 * t) =
                make_float2(sacc[ni][0], sacc[ni][1]);
            *(float2*)(Ps + (mrow + 8 + g) * AST + ni * 8 + 2 * t) =
                make_float2(sacc[ni][2], sacc[ni][3]);
        }
        __syncwarp();

        // ---- O += P @ V ----
        #pragma unroll
        for (int kc = 0; kc < 8; kc++) {
            const int k0 = kc * 8;
            uint32_t af[4];
            const float* pp = Ps + (mrow + g) * AST + k0 + t;
            af[0] = f2tf(pp[0]);
            af[2] = f2tf(pp[4]);
            af[1] = f2tf(pp[8 * AST]);
            af[3] = f2tf(pp[8 * AST + 4]);
            #pragma unroll
            for (int ni = 0; ni < 8; ni++) {
                uint32_t bf[2];
                bf[0] = f2tf(Vs[(k0 + t) * AST + ni * 8 + g]);
                bf[1] = f2tf(Vs[(k0 + t + 4) * AST + ni * 8 + g]);
                mma8(oacc[ni], af, bf);
            }
        }
    }

    // ---- epilogue ----
    const float il0 = 1.0f / l0, il1 = 1.0f / l1;
    const size_t row0 = (size_t)(b * SEQ + q0 + mrow + g);
    #pragma unroll
    for (int ni = 0; ni < 8; ni++) {
        const int col = h * HD + ni * 8 + 2 * t;
        *(float2*)(O + row0 * CDIM + col) =
            make_float2(oacc[ni][0] * il0, oacc[ni][1] * il0);
        *(float2*)(O + (row0 + 8) * CDIM + col) =
            make_float2(oacc[ni][2] * il1, oacc[ni][3] * il1);
    }
}

// =========================================================================
// launch
// =========================================================================
extern "C" void kernel_launch(void* const* d_in, const int* in_sizes, int n_in,
                              void* d_out, int out_size) {
    const float* x      = (const float*)d_in[0];
    const float* w_qkv  = (const float*)d_in[1];
    const float* w_proj = (const float*)d_in[2];
    const float* b_proj = (const float*)d_in[3];
    float* out = (float*)d_out;

    float *qkv_ptr, *o_ptr;
    cudaGetSymbolAddress((void**)&qkv_ptr, g_qkv);
    cudaGetSymbolAddress((void**)&o_ptr,   g_o);

    cudaFuncSetAttribute(gemm_tf32,
                         cudaFuncAttributeMaxDynamicSharedMemorySize, GEMM_SMEM);
    cudaFuncSetAttribute(attn_tf32,
                         cudaFuncAttributeMaxDynamicSharedMemorySize, FA_SMEM);

    // 1) QKV projection: [8192,768] @ [768,2304]
    {
        dim3 grid(QKVC / BN, MROWS / BM);
        gemm_tf32<<<grid, 256, GEMM_SMEM>>>(x, w_qkv, qkv_ptr,
                                            MROWS, QKVC, CDIM, nullptr);
    }
    // 2) flash attention
    {
        dim3 grid(SEQ / BQ, NH, B_);
        attn_tf32<<<grid, 256, FA_SMEM>>>(qkv_ptr, o_ptr);
    }
    // 3) output projection + bias: [8192,768] @ [768,768]
    {
        dim3 grid(CDIM / BN, MROWS / BM);
        gemm_tf32<<<grid, 256, GEMM_SMEM>>>(o_ptr, w_proj, out,
                                            MROWS, CDIM, CDIM, b_proj);
    }
}